// round 2
// baseline (speedup 1.0000x reference)
#include <cuda_runtime.h>
#include <cuda_bf16.h>
#include <math.h>

// ---------------------------------------------------------------------------
// WindowAttention baseline (fp32, tiled SGEMM + fused attention)
//   x:[4096,49,384] -> qkv gemm -> attn(mask, rel bias, softmax) -> proj gemm
// ---------------------------------------------------------------------------

#define BW      4096
#define NTOK    49
#define DIM     384
#define NHEAD   12
#define HD      32
#define NW      256
#define M_ROWS  (BW * NTOK)        // 200704
#define QKV_N   (3 * DIM)          // 1152

// Scratch (allocation-free rule: __device__ globals)
__device__ float g_qkv[(size_t)M_ROWS * QKV_N];   // ~925 MB
__device__ float g_att[(size_t)M_ROWS * DIM];     // ~308 MB

// ---------------------------------------------------------------------------
// SGEMM: C[M,N] = A[M,K] @ B[K,N] + bias[N]
// 128x128 tile, K-tile 8, 256 threads, 8x8 per-thread micro-tile.
// Requires M%128==0, N%128==0, K%8==0 (true for all our shapes).
// ---------------------------------------------------------------------------
__global__ __launch_bounds__(256, 2)
void sgemm_bias_kernel(const float* __restrict__ A, const float* __restrict__ B,
                       const float* __restrict__ bias, float* __restrict__ C,
                       int M, int N, int K)
{
    __shared__ float As[8][128];
    __shared__ float Bs[8][128];

    const int tid = threadIdx.x;
    const int bm = blockIdx.x * 128;
    const int bn = blockIdx.y * 128;

    const int tx = tid & 15;           // 0..15
    const int ty = tid >> 4;           // 0..15
    const int row0 = ty * 8;
    const int col0 = tx * 8;

    // A-tile load mapping: 128 rows x 8 cols = 1024 floats; one float4/thread
    const int a_row = tid >> 1;            // 0..127
    const int a_col = (tid & 1) * 4;       // 0 or 4
    // B-tile load mapping: 8 rows x 128 cols; one float4/thread
    const int b_row = tid >> 5;            // 0..7
    const int b_col = (tid & 31) * 4;      // 0..124

    const float* Aptr = A + (size_t)(bm + a_row) * K + a_col;
    const float* Bptr = B + (size_t)b_row * N + bn + b_col;

    float acc[8][8];
    #pragma unroll
    for (int i = 0; i < 8; i++)
        #pragma unroll
        for (int j = 0; j < 8; j++) acc[i][j] = 0.f;

    for (int k0 = 0; k0 < K; k0 += 8) {
        float4 av = *(const float4*)(Aptr + k0);
        float4 bv = *(const float4*)(Bptr + (size_t)k0 * N);

        As[a_col + 0][a_row] = av.x;
        As[a_col + 1][a_row] = av.y;
        As[a_col + 2][a_row] = av.z;
        As[a_col + 3][a_row] = av.w;
        *(float4*)&Bs[b_row][b_col] = bv;
        __syncthreads();

        #pragma unroll
        for (int k = 0; k < 8; k++) {
            float ar[8], br[8];
            float4 t0 = *(const float4*)&As[k][row0];
            float4 t1 = *(const float4*)&As[k][row0 + 4];
            ar[0]=t0.x; ar[1]=t0.y; ar[2]=t0.z; ar[3]=t0.w;
            ar[4]=t1.x; ar[5]=t1.y; ar[6]=t1.z; ar[7]=t1.w;
            float4 u0 = *(const float4*)&Bs[k][col0];
            float4 u1 = *(const float4*)&Bs[k][col0 + 4];
            br[0]=u0.x; br[1]=u0.y; br[2]=u0.z; br[3]=u0.w;
            br[4]=u1.x; br[5]=u1.y; br[6]=u1.z; br[7]=u1.w;
            #pragma unroll
            for (int i = 0; i < 8; i++)
                #pragma unroll
                for (int j = 0; j < 8; j++)
                    acc[i][j] = fmaf(ar[i], br[j], acc[i][j]);
        }
        __syncthreads();
    }

    // Epilogue: += bias, vectorized stores
    float bvals[8];
    #pragma unroll
    for (int j = 0; j < 8; j++) bvals[j] = bias[bn + col0 + j];

    #pragma unroll
    for (int i = 0; i < 8; i++) {
        float* crow = C + (size_t)(bm + row0 + i) * N + bn + col0;
        float4 o0, o1;
        o0.x = acc[i][0] + bvals[0]; o0.y = acc[i][1] + bvals[1];
        o0.z = acc[i][2] + bvals[2]; o0.w = acc[i][3] + bvals[3];
        o1.x = acc[i][4] + bvals[4]; o1.y = acc[i][5] + bvals[5];
        o1.z = acc[i][6] + bvals[6]; o1.w = acc[i][7] + bvals[7];
        *(float4*)(crow) = o0;
        *(float4*)(crow + 4) = o1;
    }
}

// ---------------------------------------------------------------------------
// Attention kernel: one block per (window b, head h).
//  scores = scale*q@k^T + mask[b%256] + clip(relbias,-5,5); clip(-10,10);
//  softmax rows; out = p @ v -> g_att[(b*49+i)*384 + h*32 + d]
// ---------------------------------------------------------------------------
__global__ __launch_bounds__(256)
void attn_kernel(const float* __restrict__ qkv, const float* __restrict__ mask,
                 const float* __restrict__ rel_table, const int* __restrict__ rel_index,
                 float* __restrict__ out)
{
    const int b = blockIdx.x;
    const int h = blockIdx.y;
    const int tid = threadIdx.x;
    const int warp = tid >> 5;
    const int lane = tid & 31;

    __shared__ float qs[NTOK][HD + 1];
    __shared__ float ks[NTOK][HD + 1];
    __shared__ float vs[NTOK][HD];
    __shared__ float ss[NTOK][NTOK + 1];

    const float scale = 0.1767766952966369f;   // 32^-0.5

    // Load q,k,v for this (b,h). qkv row stride 1152; q/k/v at col offset 0/384/768.
    for (int idx = tid; idx < NTOK * HD; idx += 256) {
        int i = idx >> 5;          // token
        int d = idx & 31;
        size_t base = (size_t)(b * NTOK + i) * QKV_N + h * HD + d;
        qs[i][d] = qkv[base] * scale;
        ks[i][d] = qkv[base + DIM];
        vs[i][d] = qkv[base + 2 * DIM];
    }
    __syncthreads();

    const float* mrow = mask + (size_t)(b & (NW - 1)) * (NTOK * NTOK);

    for (int idx = tid; idx < NTOK * NTOK; idx += 256) {
        int i = idx / NTOK;
        int j = idx - i * NTOK;
        float dot = 0.f;
        #pragma unroll
        for (int d = 0; d < HD; d++) dot = fmaf(qs[i][d], ks[j][d], dot);
        int ri = rel_index[idx];
        float bias = rel_table[ri * NHEAD + h];
        bias = fminf(fmaxf(bias, -5.f), 5.f);
        float val = dot + mrow[idx] + bias;
        ss[i][j] = fminf(fmaxf(val, -10.f), 10.f);
    }
    __syncthreads();

    // Softmax: warp per row (8 warps cycle over 49 rows), lane-parallel.
    for (int i = warp; i < NTOK; i += 8) {
        float m = -1e30f;
        for (int j = lane; j < NTOK; j += 32) m = fmaxf(m, ss[i][j]);
        #pragma unroll
        for (int o = 16; o > 0; o >>= 1)
            m = fmaxf(m, __shfl_xor_sync(0xffffffffu, m, o));

        float sum = 0.f;
        for (int j = lane; j < NTOK; j += 32) {
            float e = __expf(ss[i][j] - m);
            ss[i][j] = e;
            sum += e;
        }
        #pragma unroll
        for (int o = 16; o > 0; o >>= 1)
            sum += __shfl_xor_sync(0xffffffffu, sum, o);

        float inv = 1.f / sum;
        for (int j = lane; j < NTOK; j += 32) ss[i][j] *= inv;
    }
    __syncthreads();

    // out = p @ v  -> scratch laid out [Bw*N, DIM], head h at col h*32
    for (int idx = tid; idx < NTOK * HD; idx += 256) {
        int i = idx >> 5;
        int d = idx & 31;
        float o = 0.f;
        #pragma unroll
        for (int j = 0; j < NTOK; j++) o = fmaf(ss[i][j], vs[j][d], o);
        out[(size_t)(b * NTOK + i) * DIM + h * HD + d] = o;
    }
}

// ---------------------------------------------------------------------------
// Launch
// ---------------------------------------------------------------------------
extern "C" void kernel_launch(void* const* d_in, const int* in_sizes, int n_in,
                              void* d_out, int out_size)
{
    const float* x = nullptr;
    const float* mask = nullptr;
    const float* qkv_w = nullptr;
    const float* qkv_b = nullptr;
    const float* proj_w = nullptr;
    const float* proj_b = nullptr;
    const float* rel_table = nullptr;
    const int*   rel_index = nullptr;

    // All input sizes are distinct -> resolve by element count.
    for (int i = 0; i < n_in; i++) {
        switch (in_sizes[i]) {
            case 77070336: x         = (const float*)d_in[i]; break;  // [4096,49,384]
            case 614656:   mask      = (const float*)d_in[i]; break;  // [256,49,49]
            case 442368:   qkv_w     = (const float*)d_in[i]; break;  // [384,1152]
            case 1152:     qkv_b     = (const float*)d_in[i]; break;
            case 147456:   proj_w    = (const float*)d_in[i]; break;  // [384,384]
            case 384:      proj_b    = (const float*)d_in[i]; break;
            case 2028:     rel_table = (const float*)d_in[i]; break;  // [169,12]
            case 2401:     rel_index = (const int*)d_in[i];   break;  // [49,49]
            default: break;
        }
    }

    float* qkv_s = nullptr;
    float* att_s = nullptr;
    cudaGetSymbolAddress((void**)&qkv_s, g_qkv);
    cudaGetSymbolAddress((void**)&att_s, g_att);

    // 1) QKV GEMM: [200704,384] @ [384,1152] + b
    dim3 g1(M_ROWS / 128, QKV_N / 128);   // 1568 x 9
    sgemm_bias_kernel<<<g1, 256>>>(x, qkv_w, qkv_b, qkv_s, M_ROWS, QKV_N, DIM);

    // 2) Attention per (window, head)
    dim3 g2(BW, NHEAD);                   // 4096 x 12
    attn_kernel<<<g2, 256>>>(qkv_s, mask, rel_table, rel_index, att_s);

    // 3) Proj GEMM: [200704,384] @ [384,384] + b -> d_out
    dim3 g3(M_ROWS / 128, DIM / 128);     // 1568 x 3
    sgemm_bias_kernel<<<g3, 256>>>(att_s, proj_w, proj_b, (float*)d_out, M_ROWS, DIM, DIM);
}

// round 5
// speedup vs baseline: 1.8580x; 1.8580x over previous
#include <cuda_runtime.h>
#include <cuda_bf16.h>
#include <math.h>
#include <stdint.h>

// ---------------------------------------------------------------------------
// WindowAttention: tf32 tensor-core GEMMs + fused attention
//   x:[4096,49,384] -> qkv gemm -> attn(mask, rel bias, softmax) -> proj gemm
// ---------------------------------------------------------------------------

#define BW      4096
#define NTOK    49
#define DIM     384
#define NHEAD   12
#define HD      32
#define NW      256
#define M_ROWS  (BW * NTOK)        // 200704
#define QKV_N   (3 * DIM)          // 1152

// Scratch (allocation-free rule: __device__ globals)
__device__ float g_qkv[(size_t)M_ROWS * QKV_N];   // ~925 MB
__device__ float g_att[(size_t)M_ROWS * DIM];     // ~308 MB

// ---------------------------------------------------------------------------
// tf32 tensor-core GEMM: C[M,N] = A[M,K] @ B[K,N] + bias[N]
// 128x128x32 block tile, 256 threads (8 warps), warp tile 64x32,
// mma.sync.m16n8k8.tf32, double-buffered smem, ldmatrix fragment loads.
// Requires M%128==0, N%128==0, K%32==0.
// Grid: (N/128, M/128) so consecutive blocks share the A tile (L2 reuse).
// ---------------------------------------------------------------------------
#define ASTR 36   // padded row stride (floats) for both As and Bs
#define SMEM_BYTES (2 * 128 * ASTR * 4 * 2)   // 73728

__device__ __forceinline__ float f2tf(float x) {
    uint32_t r;
    asm("cvt.rna.tf32.f32 %0, %1;" : "=r"(r) : "f"(x));
    return __uint_as_float(r);
}

__global__ __launch_bounds__(256)
void tf32_gemm_bias(const float* __restrict__ A, const float* __restrict__ B,
                    const float* __restrict__ bias, float* __restrict__ C,
                    int M, int N, int K)
{
    const int tid  = threadIdx.x;
    const int lane = tid & 31;
    const int wid  = tid >> 5;
    const int warpM = wid & 1;        // 64-row half
    const int warpN = wid >> 1;       // 32-col quarter
    const int g   = lane >> 2;
    const int tig = lane & 3;

    const int bn = blockIdx.x * 128;
    const int bm = blockIdx.y * 128;

    extern __shared__ float sm[];
    float* As = sm;                    // [2][128][ASTR] row-major (m, k)
    float* Bs = sm + 2 * 128 * ASTR;   // [2][128][ASTR] n-major (n, k)

    // global->reg staging mappings
    const int ar  = tid >> 3;          // A row 0..31 (+32*i)
    const int af  = (tid & 7) * 4;     // A k offset (float4)
    const int bnn = tid & 127;         // B n within tile
    const int bkc = tid >> 7;          // 0..1 -> k-chunk = (bkc+2*i)*4

    const float* Ag = A + (size_t)bm * K;
    const float* Bg = B + bn;

    float4 aS[4], bS[4];

    // ---- prefetch tile 0 into registers
    #pragma unroll
    for (int i = 0; i < 4; i++)
        aS[i] = *(const float4*)(Ag + (size_t)(ar + 32 * i) * K + af);
    #pragma unroll
    for (int i = 0; i < 4; i++) {
        int kb = (bkc + 2 * i) * 4;
        float4 v;
        v.x = Bg[(size_t)(kb + 0) * N + bnn];
        v.y = Bg[(size_t)(kb + 1) * N + bnn];
        v.z = Bg[(size_t)(kb + 2) * N + bnn];
        v.w = Bg[(size_t)(kb + 3) * N + bnn];
        bS[i] = v;
    }

    // ---- store stage (with tf32 rounding)
    {
        float* Ab = As;  // buf 0
        float* Bb = Bs;
        #pragma unroll
        for (int i = 0; i < 4; i++) {
            float4 cv = make_float4(f2tf(aS[i].x), f2tf(aS[i].y), f2tf(aS[i].z), f2tf(aS[i].w));
            *(float4*)(Ab + (ar + 32 * i) * ASTR + af) = cv;
        }
        #pragma unroll
        for (int i = 0; i < 4; i++) {
            float4 cv = make_float4(f2tf(bS[i].x), f2tf(bS[i].y), f2tf(bS[i].z), f2tf(bS[i].w));
            *(float4*)(Bb + bnn * ASTR + (bkc + 2 * i) * 4) = cv;
        }
    }
    __syncthreads();

    float c[4][4][4] = {};

    const int nT = K / 32;
    for (int kt = 0; kt < nT; kt++) {
        const int cur = kt & 1;

        // prefetch next tile G->reg
        if (kt + 1 < nT) {
            const float* Ak = Ag + (kt + 1) * 32;
            #pragma unroll
            for (int i = 0; i < 4; i++)
                aS[i] = *(const float4*)(Ak + (size_t)(ar + 32 * i) * K + af);
            const float* Bk = Bg + (size_t)(kt + 1) * 32 * N;
            #pragma unroll
            for (int i = 0; i < 4; i++) {
                int kb = (bkc + 2 * i) * 4;
                float4 v;
                v.x = Bk[(size_t)(kb + 0) * N + bnn];
                v.y = Bk[(size_t)(kb + 1) * N + bnn];
                v.z = Bk[(size_t)(kb + 2) * N + bnn];
                v.w = Bk[(size_t)(kb + 3) * N + bnn];
                bS[i] = v;
            }
        }

        // ---- compute on buffer `cur`
        const float* Ab = As + cur * 128 * ASTR;
        const float* Bb = Bs + cur * 128 * ASTR;
        #pragma unroll
        for (int ks = 0; ks < 4; ks++) {
            uint32_t aF[4][4], bF[4][2];
            #pragma unroll
            for (int mt = 0; mt < 4; mt++) {
                int row = warpM * 64 + mt * 16 + ((lane >> 3) & 1) * 8 + (lane & 7);
                int kof = ks * 8 + (lane >> 4) * 4;
                uint32_t addr = (uint32_t)__cvta_generic_to_shared(Ab + row * ASTR + kof);
                asm volatile("ldmatrix.sync.aligned.m8n8.x4.shared.b16 {%0,%1,%2,%3}, [%4];"
                             : "=r"(aF[mt][0]), "=r"(aF[mt][1]), "=r"(aF[mt][2]), "=r"(aF[mt][3])
                             : "r"(addr));
            }
            #pragma unroll
            for (int nt = 0; nt < 4; nt++) {
                int row = warpN * 32 + nt * 8 + (lane & 7);
                int kof = ks * 8 + ((lane >> 3) & 1) * 4;
                uint32_t addr = (uint32_t)__cvta_generic_to_shared(Bb + row * ASTR + kof);
                asm volatile("ldmatrix.sync.aligned.m8n8.x2.shared.b16 {%0,%1}, [%2];"
                             : "=r"(bF[nt][0]), "=r"(bF[nt][1])
                             : "r"(addr));
            }
            #pragma unroll
            for (int mt = 0; mt < 4; mt++)
                #pragma unroll
                for (int nt = 0; nt < 4; nt++) {
                    asm volatile(
                        "mma.sync.aligned.m16n8k8.row.col.f32.tf32.tf32.f32 "
                        "{%0,%1,%2,%3}, {%4,%5,%6,%7}, {%8,%9}, {%0,%1,%2,%3};"
                        : "+f"(c[mt][nt][0]), "+f"(c[mt][nt][1]),
                          "+f"(c[mt][nt][2]), "+f"(c[mt][nt][3])
                        : "r"(aF[mt][0]), "r"(aF[mt][1]), "r"(aF[mt][2]), "r"(aF[mt][3]),
                          "r"(bF[nt][0]), "r"(bF[nt][1]));
                }
        }

        // ---- stage next tile into other buffer
        if (kt + 1 < nT) {
            float* Ao = As + (cur ^ 1) * 128 * ASTR;
            float* Bo = Bs + (cur ^ 1) * 128 * ASTR;
            #pragma unroll
            for (int i = 0; i < 4; i++) {
                float4 cv = make_float4(f2tf(aS[i].x), f2tf(aS[i].y), f2tf(aS[i].z), f2tf(aS[i].w));
                *(float4*)(Ao + (ar + 32 * i) * ASTR + af) = cv;
            }
            #pragma unroll
            for (int i = 0; i < 4; i++) {
                float4 cv = make_float4(f2tf(bS[i].x), f2tf(bS[i].y), f2tf(bS[i].z), f2tf(bS[i].w));
                *(float4*)(Bo + bnn * ASTR + (bkc + 2 * i) * 4) = cv;
            }
            __syncthreads();
        }
    }

    // ---- epilogue: += bias, float2 stores
    #pragma unroll
    for (int mt = 0; mt < 4; mt++) {
        #pragma unroll
        for (int nt = 0; nt < 4; nt++) {
            int row0 = bm + warpM * 64 + mt * 16 + g;
            int col  = bn + warpN * 32 + nt * 8 + tig * 2;
            float b0 = bias[col], b1 = bias[col + 1];
            float2 v0 = make_float2(c[mt][nt][0] + b0, c[mt][nt][1] + b1);
            float2 v1 = make_float2(c[mt][nt][2] + b0, c[mt][nt][3] + b1);
            *(float2*)&C[(size_t)row0 * N + col] = v0;
            *(float2*)&C[(size_t)(row0 + 8) * N + col] = v1;
        }
    }
}

// ---------------------------------------------------------------------------
// Attention kernel: one block per (window b, head h).
// ---------------------------------------------------------------------------
__global__ __launch_bounds__(256)
void attn_kernel(const float* __restrict__ qkv, const float* __restrict__ mask,
                 const float* __restrict__ rel_table, const int* __restrict__ rel_index,
                 float* __restrict__ out)
{
    const int b = blockIdx.x;
    const int h = blockIdx.y;
    const int tid = threadIdx.x;
    const int warp = tid >> 5;
    const int lane = tid & 31;

    __shared__ float qs[NTOK][HD + 1];
    __shared__ float ks[NTOK][HD + 1];
    __shared__ float vs[NTOK][HD];
    __shared__ float ss[NTOK][NTOK + 1];

    const float scale = 0.1767766952966369f;   // 32^-0.5

    for (int idx = tid; idx < NTOK * HD; idx += 256) {
        int i = idx >> 5;
        int d = idx & 31;
        size_t base = (size_t)(b * NTOK + i) * QKV_N + h * HD + d;
        qs[i][d] = qkv[base] * scale;
        ks[i][d] = qkv[base + DIM];
        vs[i][d] = qkv[base + 2 * DIM];
    }
    __syncthreads();

    const float* mrow = mask + (size_t)(b & (NW - 1)) * (NTOK * NTOK);

    for (int idx = tid; idx < NTOK * NTOK; idx += 256) {
        int i = idx / NTOK;
        int j = idx - i * NTOK;
        float dot = 0.f;
        #pragma unroll
        for (int d = 0; d < HD; d++) dot = fmaf(qs[i][d], ks[j][d], dot);
        int ri = rel_index[idx];
        float bias = rel_table[ri * NHEAD + h];
        bias = fminf(fmaxf(bias, -5.f), 5.f);
        float val = dot + mrow[idx] + bias;
        ss[i][j] = fminf(fmaxf(val, -10.f), 10.f);
    }
    __syncthreads();

    // Softmax: warp per row
    for (int i = warp; i < NTOK; i += 8) {
        float m = -1e30f;
        for (int j = lane; j < NTOK; j += 32) m = fmaxf(m, ss[i][j]);
        #pragma unroll
        for (int o = 16; o > 0; o >>= 1)
            m = fmaxf(m, __shfl_xor_sync(0xffffffffu, m, o));

        float sum = 0.f;
        for (int j = lane; j < NTOK; j += 32) {
            float e = __expf(ss[i][j] - m);
            ss[i][j] = e;
            sum += e;
        }
        #pragma unroll
        for (int o = 16; o > 0; o >>= 1)
            sum += __shfl_xor_sync(0xffffffffu, sum, o);

        float inv = 1.f / sum;
        for (int j = lane; j < NTOK; j += 32) ss[i][j] *= inv;
    }
    __syncthreads();

    for (int idx = tid; idx < NTOK * HD; idx += 256) {
        int i = idx >> 5;
        int d = idx & 31;
        float o = 0.f;
        #pragma unroll
        for (int j = 0; j < NTOK; j++) o = fmaf(ss[i][j], vs[j][d], o);
        out[(size_t)(b * NTOK + i) * DIM + h * HD + d] = o;
    }
}

// ---------------------------------------------------------------------------
// Launch
// ---------------------------------------------------------------------------
extern "C" void kernel_launch(void* const* d_in, const int* in_sizes, int n_in,
                              void* d_out, int out_size)
{
    const float* x = nullptr;
    const float* mask = nullptr;
    const float* qkv_w = nullptr;
    const float* qkv_b = nullptr;
    const float* proj_w = nullptr;
    const float* proj_b = nullptr;
    const float* rel_table = nullptr;
    const int*   rel_index = nullptr;

    for (int i = 0; i < n_in; i++) {
        switch (in_sizes[i]) {
            case 77070336: x         = (const float*)d_in[i]; break;  // [4096,49,384]
            case 614656:   mask      = (const float*)d_in[i]; break;  // [256,49,49]
            case 442368:   qkv_w     = (const float*)d_in[i]; break;  // [384,1152]
            case 1152:     qkv_b     = (const float*)d_in[i]; break;
            case 147456:   proj_w    = (const float*)d_in[i]; break;  // [384,384]
            case 384:      proj_b    = (const float*)d_in[i]; break;
            case 2028:     rel_table = (const float*)d_in[i]; break;  // [169,12]
            case 2401:     rel_index = (const int*)d_in[i];   break;  // [49,49]
            default: break;
        }
    }

    float* qkv_s = nullptr;
    float* att_s = nullptr;
    cudaGetSymbolAddress((void**)&qkv_s, g_qkv);
    cudaGetSymbolAddress((void**)&att_s, g_att);

    cudaFuncSetAttribute(tf32_gemm_bias, cudaFuncAttributeMaxDynamicSharedMemorySize, SMEM_BYTES);

    // 1) QKV GEMM: [200704,384] @ [384,1152] + b   (grid x = N-tiles for A reuse)
    dim3 g1(QKV_N / 128, M_ROWS / 128);   // 9 x 1568
    tf32_gemm_bias<<<g1, 256, SMEM_BYTES>>>(x, qkv_w, qkv_b, qkv_s, M_ROWS, QKV_N, DIM);

    // 2) Attention per (window, head)
    dim3 g2(BW, NHEAD);                   // 4096 x 12
    attn_kernel<<<g2, 256>>>(qkv_s, mask, rel_table, rel_index, att_s);

    // 3) Proj GEMM: [200704,384] @ [384,384] + b -> d_out
    dim3 g3(DIM / 128, M_ROWS / 128);     // 3 x 1568
    tf32_gemm_bias<<<g3, 256, SMEM_BYTES>>>(att_s, proj_w, proj_b, (float*)d_out, M_ROWS, DIM, DIM);
}